// round 5
// baseline (speedup 1.0000x reference)
#include <cuda_runtime.h>
#include <cstdint>

#define V_VARS 256
#define N_PER_VAR 16
#define C_CATS 256
#define B_BATCH 4096
#define NUM_NODES (V_VARS * N_PER_VAR)
#define NCHUNKS 2
#define BCHUNK (B_BATCH / NCHUNKS)       // 2048 = 256 threads * 4 * 2 iters
#define NGROUPS (N_PER_VAR / 4)          // 4 groups of 4 nodes

__global__ __launch_bounds__(256, 4)
void categorical_kernel(
    const int* __restrict__ data,      // [V, B] int32
    const int* __restrict__ vids,      // [NUM_NODES] int32
    const int* __restrict__ psids,     // [NUM_NODES] int32
    const float* __restrict__ params,  // [NUM_NODES * C]
    const int* __restrict__ mask,      // [V, B] bool -> int32
    const float* __restrict__ alphas,  // [V, B]
    float* __restrict__ out)           // [NUM_NODES, B]
{
    // sp4[g][c] holds params of nodes 4g..4g+3 at category c (float4) — 16 KB
    __shared__ float4 sp4[NGROUPS][C_CATS];

    const int tid   = threadIdx.x;
    const int vblk  = blockIdx.x >> 1;            // variable index (0..255)
    const int chunk = blockIdx.x & (NCHUNKS - 1);
    const int n0    = vblk * N_PER_VAR;
    const int v     = vids[n0];

    // Stage params transposed: 4 coalesced row reads per group, pack to float4.
    #pragma unroll
    for (int g = 0; g < NGROUPS; ++g) {
        float4 p;
        p.x = params[psids[n0 + 4 * g + 0] + tid];
        p.y = params[psids[n0 + 4 * g + 1] + tid];
        p.z = params[psids[n0 + 4 * g + 2] + tid];
        p.w = params[psids[n0 + 4 * g + 3] + tid];
        sp4[g][tid] = p;
    }
    __syncthreads();

    const int*   __restrict__ drow = data   + v * B_BATCH;
    const int*   __restrict__ mrow = mask   + v * B_BATCH;
    const float* __restrict__ arow = alphas + v * B_BATCH;

    #pragma unroll
    for (int it = 0; it < BCHUNK / (256 * 4); ++it) {
        const int b = chunk * BCHUNK + it * (256 * 4) + tid * 4;

        int4   d4 = *reinterpret_cast<const int4*>(drow + b);
        int4   m4 = *reinterpret_cast<const int4*>(mrow + b);
        float4 a4 = *reinterpret_cast<const float4*>(arow + b);

        const float c0 = 1.0f - a4.x;
        const float c1 = 1.0f - a4.y;
        const float c2 = 1.0f - a4.z;
        const float c3 = 1.0f - a4.w;

        float* obase = out + (long long)n0 * B_BATCH + b;

        #pragma unroll
        for (int g = 0; g < NGROUPS; ++g) {
            // 4 nodes' params for each of the 4 batch elements: 4x LDS.128
            float4 pa = sp4[g][d4.x];
            float4 pb = sp4[g][d4.y];
            float4 pc = sp4[g][d4.z];
            float4 pd = sp4[g][d4.w];

            const float* fa = reinterpret_cast<const float*>(&pa);
            const float* fb = reinterpret_cast<const float*>(&pb);
            const float* fc = reinterpret_cast<const float*>(&pc);
            const float* fd = reinterpret_cast<const float*>(&pd);

            #pragma unroll
            for (int j = 0; j < 4; ++j) {
                float4 r;
                r.x = m4.x ? 0.0f : __logf(fmaxf(fa[j], 1e-10f) * a4.x + c0);
                r.y = m4.y ? 0.0f : __logf(fmaxf(fb[j], 1e-10f) * a4.y + c1);
                r.z = m4.z ? 0.0f : __logf(fmaxf(fc[j], 1e-10f) * a4.z + c2);
                r.w = m4.w ? 0.0f : __logf(fmaxf(fd[j], 1e-10f) * a4.w + c3);
                *reinterpret_cast<float4*>(obase + (long long)(4 * g + j) * B_BATCH) = r;
            }
        }
    }
}

extern "C" void kernel_launch(void* const* d_in, const int* in_sizes, int n_in,
                              void* d_out, int out_size) {
    const int* data     = (const int*)d_in[0];
    const int* vids     = (const int*)d_in[1];
    const int* psids    = (const int*)d_in[2];
    const float* params = (const float*)d_in[3];
    const int* mm       = (const int*)d_in[4];
    const float* alphas = (const float*)d_in[5];
    float* out          = (float*)d_out;

    categorical_kernel<<<V_VARS * NCHUNKS, 256>>>(data, vids, psids, params, mm, alphas, out);
}

// round 6
// speedup vs baseline: 1.3636x; 1.3636x over previous
#include <cuda_runtime.h>
#include <cstdint>

#define V_VARS 256
#define N_PER_VAR 16
#define C_CATS 256
#define B_BATCH 4096
#define NUM_NODES (V_VARS * N_PER_VAR)
#define NCHUNKS 4
#define BCHUNK (B_BATCH / NCHUNKS)   // 1024 = 256 threads * 4

__global__ __launch_bounds__(256, 6)
void categorical_kernel(
    const int* __restrict__ data,      // [V, B] int32
    const int* __restrict__ vids,      // [NUM_NODES] int32
    const int* __restrict__ psids,     // [NUM_NODES] int32
    const float* __restrict__ params,  // [NUM_NODES * C]
    const int* __restrict__ mask,      // [V, B] bool -> int32
    const float* __restrict__ alphas,  // [V, B]
    float* __restrict__ out)           // [NUM_NODES, B]
{
    __shared__ float sp[N_PER_VAR][C_CATS];   // 16 KB

    const int tid   = threadIdx.x;
    const int vblk  = blockIdx.x >> 2;        // variable index (0..255)
    const int chunk = blockIdx.x & (NCHUNKS - 1);
    const int n0    = vblk * N_PER_VAR;
    const int v     = vids[n0];

    // Stage the 16 param rows (1 KB each) into shared. 256 threads = 1 row/iter.
    #pragma unroll
    for (int c = 0; c < N_PER_VAR; ++c) {
        sp[c][tid] = params[psids[n0 + c] + tid];
    }
    __syncthreads();

    const int b = chunk * BCHUNK + tid * 4;

    const int*   __restrict__ drow = data   + v * B_BATCH;
    const int*   __restrict__ mrow = mask   + v * B_BATCH;
    const float* __restrict__ arow = alphas + v * B_BATCH;

    int4   d4 = *reinterpret_cast<const int4*>(drow + b);
    int4   m4 = *reinterpret_cast<const int4*>(mrow + b);
    float4 a4 = *reinterpret_cast<const float4*>(arow + b);

    const float c0 = 1.0f - a4.x;
    const float c1 = 1.0f - a4.y;
    const float c2 = 1.0f - a4.z;
    const float c3 = 1.0f - a4.w;

    float* orow = out + n0 * B_BATCH + b;     // int32 addressing (fits 2^31)

    #pragma unroll
    for (int c = 0; c < N_PER_VAR; ++c) {
        // scalar LDS gathers, consumed immediately (low register pressure)
        float g0 = m4.x ? 1.0f : fmaf(fmaxf(sp[c][d4.x], 1e-10f), a4.x, c0);
        float g1 = m4.y ? 1.0f : fmaf(fmaxf(sp[c][d4.y], 1e-10f), a4.y, c1);
        float g2 = m4.z ? 1.0f : fmaf(fmaxf(sp[c][d4.z], 1e-10f), a4.z, c2);
        float g3 = m4.w ? 1.0f : fmaf(fmaxf(sp[c][d4.w], 1e-10f), a4.w, c3);

        float4 r;
        r.x = __logf(g0);   // log(1) == 0 handles the masked case
        r.y = __logf(g1);
        r.z = __logf(g2);
        r.w = __logf(g3);

        *reinterpret_cast<float4*>(orow) = r;
        orow += B_BATCH;
    }
}

extern "C" void kernel_launch(void* const* d_in, const int* in_sizes, int n_in,
                              void* d_out, int out_size) {
    const int* data     = (const int*)d_in[0];
    const int* vids     = (const int*)d_in[1];
    const int* psids    = (const int*)d_in[2];
    const float* params = (const float*)d_in[3];
    const int* mm       = (const int*)d_in[4];
    const float* alphas = (const float*)d_in[5];
    float* out          = (float*)d_out;

    categorical_kernel<<<V_VARS * NCHUNKS, 256>>>(data, vids, psids, params, mm, alphas, out);
}